// round 14
// baseline (speedup 1.0000x reference)
#include <cuda_runtime.h>
#include <cuda_bf16.h>
#include <math.h>
#include <stdint.h>

#define N_NODES   50000
#define N_EDGES   800000
#define HID       128
#define N_GRAPHS  256
#define OUT_F     8
#define NEG_SLOPE 0.2f

#define SCAN_BLK  1024
#define N_SBLK    ((N_NODES + SCAN_BLK - 1) / SCAN_BLK)   // 49

// ---------------------------------------------------------------------------
// Scratch (device globals: no allocation allowed in kernel_launch)
// ---------------------------------------------------------------------------
__device__ float g_h [(size_t)N_NODES * HID];   // GEMM output / aggregation input
__device__ float g_xb[(size_t)N_NODES * HID];   // aggregation output / next GEMM input
__device__ float g_as[N_NODES];
__device__ float g_ad[N_NODES];
__device__ int   g_deg[N_NODES];
__device__ int   g_rowptr[N_NODES + 1];
__device__ int   g_woff[N_NODES];
__device__ int   g_bsum[N_SBLK];
__device__ int   g_boff[N_SBLK];
__device__ int   g_srcA[N_EDGES];
__device__ int   g_dstA[N_EDGES];
__device__ int   g_esrc[N_EDGES];               // src per edge, sorted by dst (CSR)
__device__ int   g_flag;                        // 1 = indices are int64, 0 = int32

// ---------------------------------------------------------------------------
// dtype detection: sample odd int32 words of edge_index.
// ---------------------------------------------------------------------------
__global__ void detect_kernel(const void* eidx) {
    const int* p = (const int*)eidx;
    int lane = threadIdx.x;
    int nz = 0;
    for (int i = lane; i < 256; i += 32) {
        long long pos = (long long)i * (2LL * N_EDGES / 256);
        nz |= (p[pos | 1] != 0);
    }
    unsigned b = __ballot_sync(0xFFFFFFFFu, nz);
    if (lane == 0) g_flag = (b == 0) ? 1 : 0;
}

// convert edge_index to int32 src/dst + dst histogram in one pass
__global__ void convert_hist_kernel(const void* eidx) {
    int e = blockIdx.x * blockDim.x + threadIdx.x;
    if (e >= N_EDGES) return;
    int s, d;
    if (g_flag) {
        const long long* p = (const long long*)eidx;
        s = (int)p[e];
        d = (int)p[e + N_EDGES];
    } else {
        const int* p = (const int*)eidx;
        s = p[e];
        d = p[e + N_EDGES];
    }
    g_srcA[e] = s;
    g_dstA[e] = d;
    atomicAdd(&g_deg[d], 1);
}

// ---------------------------------------------------------------------------
// Multi-block exclusive scan of g_deg -> g_rowptr / g_woff  (3 stages)
// ---------------------------------------------------------------------------
__global__ __launch_bounds__(SCAN_BLK)
void scan1_kernel() {
    __shared__ int s[SCAN_BLK];
    const int t = threadIdx.x;
    const int i = blockIdx.x * SCAN_BLK + t;
    int v = (i < N_NODES) ? g_deg[i] : 0;
    s[t] = v;
    __syncthreads();
    #pragma unroll
    for (int off = 1; off < SCAN_BLK; off <<= 1) {
        int u = (t >= off) ? s[t - off] : 0;
        __syncthreads();
        s[t] += u;
        __syncthreads();
    }
    if (i < N_NODES) g_rowptr[i] = s[t] - v;
    if (t == SCAN_BLK - 1) g_bsum[blockIdx.x] = s[t];
}

__global__ __launch_bounds__(64)
void scan2_kernel() {
    __shared__ int s[64];
    const int t = threadIdx.x;
    int v = (t < N_SBLK) ? g_bsum[t] : 0;
    s[t] = v;
    __syncthreads();
    #pragma unroll
    for (int off = 1; off < 64; off <<= 1) {
        int u = (t >= off) ? s[t - off] : 0;
        __syncthreads();
        s[t] += u;
        __syncthreads();
    }
    if (t < N_SBLK) g_boff[t] = s[t] - v;
}

__global__ __launch_bounds__(SCAN_BLK)
void scan3_kernel() {
    const int i = blockIdx.x * SCAN_BLK + threadIdx.x;
    if (i < N_NODES) {
        int r = g_rowptr[i] + g_boff[blockIdx.x];
        g_rowptr[i] = r;
        g_woff[i]   = r;
    }
    if (i == 0) g_rowptr[N_NODES] = N_EDGES;
}

__global__ void scatter_kernel() {
    int e = blockIdx.x * blockDim.x + threadIdx.x;
    if (e >= N_EDGES) return;
    int d = g_dstA[e];
    int p = atomicAdd(&g_woff[d], 1);
    g_esrc[p] = g_srcA[e];
}

// ---------------------------------------------------------------------------
// Tensor-core GEMM via mma.sync (sm_80+ baseline feature, valid on compute_103):
// C[M,128] = A[M,K] @ B[K,128], fp32 in/out.
// Split bf16: A=Ah+Al, B=Bh+Bl; D += Ah*Bh + Ah*Bl + Al*Bh (fp32 accum).
// BM=BN=128, BK=32; 8 warps (2x4), warp tile 64x32 = 4x4 m16n8k16 frags.
// Fused epilogue: g_as[m]=C[m,:]@aw, g_ad[m]=C[m,:]@dw via SMEM stage.
// ---------------------------------------------------------------------------
#define GEMM_THREADS 256
#define PAD_A 40
#define PAD_B 36
#define SM_AH 0
#define SM_AL (SM_AH + 128 * PAD_A * 2)      // 10240
#define SM_BH (SM_AL + 128 * PAD_A * 2)      // 20480
#define SM_BL (SM_BH + 128 * PAD_B * 2)      // 29696
#define STAGE_STRIDE 129
#define SM_TOTAL (128 * STAGE_STRIDE * 4)    // 66048 (stage unions over operands)

__device__ __forceinline__ void mma16816(float* d,
                                         uint32_t a0, uint32_t a1, uint32_t a2, uint32_t a3,
                                         uint32_t b0, uint32_t b1) {
    asm volatile(
        "mma.sync.aligned.m16n8k16.row.col.f32.bf16.bf16.f32 "
        "{%0,%1,%2,%3}, {%4,%5,%6,%7}, {%8,%9}, {%0,%1,%2,%3};"
        : "+f"(d[0]), "+f"(d[1]), "+f"(d[2]), "+f"(d[3])
        : "r"(a0), "r"(a1), "r"(a2), "r"(a3), "r"(b0), "r"(b1));
}

template <int K>
__global__ __launch_bounds__(GEMM_THREADS, 1)
void mma_gemm_kernel(const float* __restrict__ A, const float* __restrict__ B,
                     float* __restrict__ C,
                     const float* __restrict__ aw, const float* __restrict__ dw,
                     int M) {
    extern __shared__ char smem[];
    __nv_bfloat16* AH = (__nv_bfloat16*)(smem + SM_AH);
    __nv_bfloat16* AL = (__nv_bfloat16*)(smem + SM_AL);
    __nv_bfloat16* BH = (__nv_bfloat16*)(smem + SM_BH);
    __nv_bfloat16* BL = (__nv_bfloat16*)(smem + SM_BL);

    const int tid  = threadIdx.x;
    const int wid  = tid >> 5;
    const int lane = tid & 31;
    const int wm   = wid >> 2;          // 0..1  (64 rows each)
    const int wn   = wid & 3;           // 0..3  (32 cols each)
    const int lr   = lane >> 2;         // group id 0..7
    const int lc   = (lane & 3) << 1;   // 0,2,4,6
    const int m0   = blockIdx.x * 128;

    float acc[4][4][4] = {};

    #pragma unroll 1
    for (int k0 = 0; k0 < K; k0 += 32) {
        __syncthreads();   // previous chunk's fragment reads complete
        // --- fill A chunk: 128 rows x 32 k, bf16 hi/lo (8 float2 per thread) ---
        #pragma unroll
        for (int i = tid; i < 128 * 16; i += GEMM_THREADS) {
            int r  = i >> 4;
            int kk = (i & 15) << 1;
            float2 v = make_float2(0.f, 0.f);
            if (m0 + r < M)
                v = *(const float2*)&A[(size_t)(m0 + r) * K + k0 + kk];
            __nv_bfloat16 hx = __float2bfloat16(v.x);
            __nv_bfloat16 hy = __float2bfloat16(v.y);
            __nv_bfloat16 lx = __float2bfloat16(v.x - __bfloat162float(hx));
            __nv_bfloat16 ly = __float2bfloat16(v.y - __bfloat162float(hy));
            *(__nv_bfloat162*)&AH[r * PAD_A + kk] = __halves2bfloat162(hx, hy);
            *(__nv_bfloat162*)&AL[r * PAD_A + kk] = __halves2bfloat162(lx, ly);
        }
        // --- fill B chunk transposed: Bs[n][k] = B[(k0+k)*HID + n] ---
        #pragma unroll
        for (int i = tid; i < 128 * 16; i += GEMM_THREADS) {
            int n  = i & 127;
            int kk = (i >> 7) << 1;
            float vx = B[(size_t)(k0 + kk)     * HID + n];
            float vy = B[(size_t)(k0 + kk + 1) * HID + n];
            __nv_bfloat16 hx = __float2bfloat16(vx);
            __nv_bfloat16 hy = __float2bfloat16(vy);
            __nv_bfloat16 lx = __float2bfloat16(vx - __bfloat162float(hx));
            __nv_bfloat16 ly = __float2bfloat16(vy - __bfloat162float(hy));
            *(__nv_bfloat162*)&BH[n * PAD_B + kk] = __halves2bfloat162(hx, hy);
            *(__nv_bfloat162*)&BL[n * PAD_B + kk] = __halves2bfloat162(lx, ly);
        }
        __syncthreads();

        // --- MMA over this chunk: 2 k-steps of 16 ---
        #pragma unroll
        for (int ks = 0; ks < 32; ks += 16) {
            uint32_t bh[4][2], bl[4][2];
            #pragma unroll
            for (int nt = 0; nt < 4; nt++) {
                int n = wn * 32 + nt * 8 + lr;
                const __nv_bfloat16* ph = BH + n * PAD_B + lc + ks;
                const __nv_bfloat16* pl = BL + n * PAD_B + lc + ks;
                bh[nt][0] = *(const uint32_t*)ph;
                bh[nt][1] = *(const uint32_t*)(ph + 8);
                bl[nt][0] = *(const uint32_t*)pl;
                bl[nt][1] = *(const uint32_t*)(pl + 8);
            }
            #pragma unroll
            for (int mt = 0; mt < 4; mt++) {
                int r = wm * 64 + mt * 16 + lr;
                const __nv_bfloat16* ph = AH + r * PAD_A + lc + ks;
                const __nv_bfloat16* pl = AL + r * PAD_A + lc + ks;
                uint32_t a0 = *(const uint32_t*)ph;
                uint32_t a1 = *(const uint32_t*)(ph + 8 * PAD_A);
                uint32_t a2 = *(const uint32_t*)(ph + 8);
                uint32_t a3 = *(const uint32_t*)(ph + 8 * PAD_A + 8);
                uint32_t l0 = *(const uint32_t*)pl;
                uint32_t l1 = *(const uint32_t*)(pl + 8 * PAD_A);
                uint32_t l2 = *(const uint32_t*)(pl + 8);
                uint32_t l3 = *(const uint32_t*)(pl + 8 * PAD_A + 8);
                #pragma unroll
                for (int nt = 0; nt < 4; nt++) {
                    mma16816(acc[mt][nt], a0, a1, a2, a3, bh[nt][0], bh[nt][1]);
                    mma16816(acc[mt][nt], a0, a1, a2, a3, bl[nt][0], bl[nt][1]);
                    mma16816(acc[mt][nt], l0, l1, l2, l3, bh[nt][0], bh[nt][1]);
                }
            }
        }
    }
    __syncthreads();

    // --- stage C tile in SMEM (fp32, padded) ---
    float* stage = (float*)smem;
    #pragma unroll
    for (int mt = 0; mt < 4; mt++) {
        int r = wm * 64 + mt * 16 + lr;
        #pragma unroll
        for (int nt = 0; nt < 4; nt++) {
            int c = wn * 32 + nt * 8 + lc;
            stage[r * STAGE_STRIDE + c]           = acc[mt][nt][0];
            stage[r * STAGE_STRIDE + c + 1]       = acc[mt][nt][1];
            stage[(r + 8) * STAGE_STRIDE + c]     = acc[mt][nt][2];
            stage[(r + 8) * STAGE_STRIDE + c + 1] = acc[mt][nt][3];
        }
    }
    __syncthreads();

    // --- fused alpha dots (one thread per row) ---
    if (tid < 128) {
        float s = 0.f, d = 0.f;
        #pragma unroll 16
        for (int c = 0; c < HID; c++) {
            float v = stage[tid * STAGE_STRIDE + c];
            s = fmaf(v, aw[c], s);
            d = fmaf(v, dw[c], d);
        }
        if (m0 + tid < M) {
            g_as[m0 + tid] = s;
            g_ad[m0 + tid] = d;
        }
    }
    // --- coalesced C store ---
    #pragma unroll 4
    for (int idx = tid; idx < 128 * 128; idx += GEMM_THREADS) {
        int r = idx >> 7;
        int c = idx & 127;
        if (m0 + r < M)
            C[(size_t)(m0 + r) * HID + c] = stage[r * STAGE_STRIDE + c];
    }
}

// ---------------------------------------------------------------------------
// Segment softmax + weighted aggregation, one warp per node (no atomics).
// ---------------------------------------------------------------------------
#define NPB 8
#define DEG_CAP 96
__global__ __launch_bounds__(256)
void gat_agg_kernel(const float* __restrict__ h,
                    const float* __restrict__ bias,
                    float* __restrict__ xout, int do_relu) {
    __shared__ float cache[NPB][DEG_CAP];
    const int warp = threadIdx.x >> 5;
    const int lane = threadIdx.x & 31;
    const int node = blockIdx.x * NPB + warp;
    if (node >= N_NODES) return;

    const int beg = g_rowptr[node];
    const int end = g_rowptr[node + 1];
    const int deg = end - beg;
    const int col = lane * 4;

    float4 acc = make_float4(0.f, 0.f, 0.f, 0.f);

    if (deg > 0) {
        const float adn = g_ad[node];
        float m = -3.0e38f;
        if (deg <= DEG_CAP) {
            for (int j = lane; j < deg; j += 32) {
                float l = g_as[g_esrc[beg + j]] + adn;
                l = fmaxf(l, NEG_SLOPE * l);
                cache[warp][j] = l;
                m = fmaxf(m, l);
            }
            #pragma unroll
            for (int o = 16; o; o >>= 1) m = fmaxf(m, __shfl_xor_sync(0xFFFFFFFFu, m, o));
            __syncwarp();
            float ss = 0.f;
            for (int j = lane; j < deg; j += 32) {
                float e = __expf(cache[warp][j] - m);
                cache[warp][j] = e;
                ss += e;
            }
            #pragma unroll
            for (int o = 16; o; o >>= 1) ss += __shfl_xor_sync(0xFFFFFFFFu, ss, o);
            const float inv = 1.0f / ss;
            __syncwarp();

            int j = 0;
            for (; j + 4 <= deg; j += 4) {
                int b0 = beg + j;
                int s0 = g_esrc[b0 + 0], s1 = g_esrc[b0 + 1];
                int s2 = g_esrc[b0 + 2], s3 = g_esrc[b0 + 3];
                float c0 = cache[warp][j + 0] * inv;
                float c1 = cache[warp][j + 1] * inv;
                float c2 = cache[warp][j + 2] * inv;
                float c3 = cache[warp][j + 3] * inv;
                float4 h0 = *(const float4*)&h[(size_t)s0 * HID + col];
                float4 h1 = *(const float4*)&h[(size_t)s1 * HID + col];
                float4 h2 = *(const float4*)&h[(size_t)s2 * HID + col];
                float4 h3 = *(const float4*)&h[(size_t)s3 * HID + col];
                acc.x = fmaf(c0, h0.x, fmaf(c1, h1.x, fmaf(c2, h2.x, fmaf(c3, h3.x, acc.x))));
                acc.y = fmaf(c0, h0.y, fmaf(c1, h1.y, fmaf(c2, h2.y, fmaf(c3, h3.y, acc.y))));
                acc.z = fmaf(c0, h0.z, fmaf(c1, h1.z, fmaf(c2, h2.z, fmaf(c3, h3.z, acc.z))));
                acc.w = fmaf(c0, h0.w, fmaf(c1, h1.w, fmaf(c2, h2.w, fmaf(c3, h3.w, acc.w))));
            }
            for (; j < deg; j++) {
                int s = g_esrc[beg + j];
                float c = cache[warp][j] * inv;
                float4 hv = *(const float4*)&h[(size_t)s * HID + col];
                acc.x = fmaf(c, hv.x, acc.x);
                acc.y = fmaf(c, hv.y, acc.y);
                acc.z = fmaf(c, hv.z, acc.z);
                acc.w = fmaf(c, hv.w, acc.w);
            }
        } else {
            for (int j = lane; j < deg; j += 32) {
                float l = g_as[g_esrc[beg + j]] + adn;
                l = fmaxf(l, NEG_SLOPE * l);
                m = fmaxf(m, l);
            }
            #pragma unroll
            for (int o = 16; o; o >>= 1) m = fmaxf(m, __shfl_xor_sync(0xFFFFFFFFu, m, o));
            float ss = 0.f;
            for (int j = lane; j < deg; j += 32) {
                float l = g_as[g_esrc[beg + j]] + adn;
                l = fmaxf(l, NEG_SLOPE * l);
                ss += __expf(l - m);
            }
            #pragma unroll
            for (int o = 16; o; o >>= 1) ss += __shfl_xor_sync(0xFFFFFFFFu, ss, o);
            const float inv = 1.0f / ss;
            for (int j = 0; j < deg; j++) {
                int s = g_esrc[beg + j];
                float l = g_as[s] + adn;
                l = fmaxf(l, NEG_SLOPE * l);
                float c = __expf(l - m) * inv;
                float4 hv = *(const float4*)&h[(size_t)s * HID + col];
                acc.x = fmaf(c, hv.x, acc.x);
                acc.y = fmaf(c, hv.y, acc.y);
                acc.z = fmaf(c, hv.z, acc.z);
                acc.w = fmaf(c, hv.w, acc.w);
            }
        }
    }

    float4 b4 = *(const float4*)&bias[col];
    float4 o;
    o.x = acc.x + b4.x;
    o.y = acc.y + b4.y;
    o.z = acc.z + b4.z;
    o.w = acc.w + b4.w;
    if (do_relu) {
        o.x = fmaxf(o.x, 0.f);
        o.y = fmaxf(o.y, 0.f);
        o.z = fmaxf(o.z, 0.f);
        o.w = fmaxf(o.w, 0.f);
    }
    *(float4*)&xout[(size_t)node * HID + col] = o;
}

// ---------------------------------------------------------------------------
// Mean-pool per graph (batch sorted -> binary search bounds) + linear head
// ---------------------------------------------------------------------------
__device__ __forceinline__ long long batch_val(const void* p, int i) {
    return g_flag ? ((const long long*)p)[i] : (long long)((const int*)p)[i];
}
__device__ int lower_bound_batch(const void* p, long long v) {
    int lo = 0, hi = N_NODES;
    while (lo < hi) {
        int mid = (lo + hi) >> 1;
        if (batch_val(p, mid) < v) lo = mid + 1; else hi = mid;
    }
    return lo;
}

__global__ __launch_bounds__(128)
void pool_head_kernel(const float* __restrict__ hfin, const void* __restrict__ batch,
                      const float* __restrict__ lin_w, const float* __restrict__ lin_b,
                      float* __restrict__ out) {
    const int g = blockIdx.x;
    const int j = threadIdx.x;
    const int lo = lower_bound_batch(batch, (long long)g);
    const int hi = lower_bound_batch(batch, (long long)g + 1);
    float sum = 0.f;
    for (int n = lo; n < hi; n++) sum += hfin[(size_t)n * HID + j];
    float cnt = (float)(hi - lo);
    __shared__ float sp[HID];
    sp[j] = sum / fmaxf(cnt, 1.0f);
    __syncthreads();
    if (j < OUT_F) {
        float acc = lin_b[j];
        #pragma unroll 16
        for (int k = 0; k < HID; k++) acc = fmaf(sp[k], lin_w[k * OUT_F + j], acc);
        out[g * OUT_F + j] = acc;
    }
}

// ---------------------------------------------------------------------------
// Launch
// ---------------------------------------------------------------------------
extern "C" void kernel_launch(void* const* d_in, const int* in_sizes, int n_in,
                              void* d_out, int out_size) {
    const float* x      = (const float*)d_in[0];
    const void*  eidx   = d_in[1];
    // d_in[2] edge_attr unused (reference else-branch)
    const void*  batch  = d_in[3];
    const float* W0     = (const float*)d_in[4];
    const float* asw0   = (const float*)d_in[5];
    const float* adw0   = (const float*)d_in[6];
    const float* b0     = (const float*)d_in[7];
    const float* W1     = (const float*)d_in[8];
    const float* asw1   = (const float*)d_in[9];
    const float* adw1   = (const float*)d_in[10];
    const float* b1     = (const float*)d_in[11];
    const float* W2     = (const float*)d_in[12];
    const float* asw2   = (const float*)d_in[13];
    const float* adw2   = (const float*)d_in[14];
    const float* b2     = (const float*)d_in[15];
    const float* lin_w  = (const float*)d_in[16];
    const float* lin_b  = (const float*)d_in[17];
    float* out = (float*)d_out;

    float* d_h;   cudaGetSymbolAddress((void**)&d_h,   g_h);
    float* d_xb;  cudaGetSymbolAddress((void**)&d_xb,  g_xb);
    int*   d_deg; cudaGetSymbolAddress((void**)&d_deg, g_deg);

    static int attr_set = 0;
    if (!attr_set) {
        cudaFuncSetAttribute(mma_gemm_kernel<256>,
                             cudaFuncAttributeMaxDynamicSharedMemorySize, SM_TOTAL);
        cudaFuncSetAttribute(mma_gemm_kernel<128>,
                             cudaFuncAttributeMaxDynamicSharedMemorySize, SM_TOTAL);
        attr_set = 1;
    }

    const int EB = (N_EDGES + 255) / 256;
    const int MB = (N_NODES + 127) / 128;       // 391 GEMM tiles
    const int GB = (N_NODES + NPB - 1) / NPB;

    // --- graph preprocessing (per launch, deterministic) ---
    detect_kernel<<<1, 32>>>(eidx);
    cudaMemsetAsync(d_deg, 0, N_NODES * sizeof(int));
    convert_hist_kernel<<<EB, 256>>>(eidx);
    scan1_kernel<<<N_SBLK, SCAN_BLK>>>();
    scan2_kernel<<<1, 64>>>();
    scan3_kernel<<<N_SBLK, SCAN_BLK>>>();
    scatter_kernel<<<EB, 256>>>();

    // --- layer 0 ---
    mma_gemm_kernel<256><<<MB, GEMM_THREADS, SM_TOTAL>>>(x, W0, d_h, asw0, adw0, N_NODES);
    gat_agg_kernel<<<GB, 256>>>(d_h, b0, d_xb, 1);
    // --- layer 1 ---
    mma_gemm_kernel<128><<<MB, GEMM_THREADS, SM_TOTAL>>>(d_xb, W1, d_h, asw1, adw1, N_NODES);
    gat_agg_kernel<<<GB, 256>>>(d_h, b1, d_xb, 1);
    // --- layer 2 (no relu) ---
    mma_gemm_kernel<128><<<MB, GEMM_THREADS, SM_TOTAL>>>(d_xb, W2, d_h, asw2, adw2, N_NODES);
    gat_agg_kernel<<<GB, 256>>>(d_h, b2, d_xb, 0);

    // --- pooling + head ---
    pool_head_kernel<<<N_GRAPHS, 128>>>(d_xb, batch, lin_w, lin_b, out);
}

// round 17
// speedup vs baseline: 1.1821x; 1.1821x over previous
#include <cuda_runtime.h>
#include <cuda_bf16.h>
#include <math.h>
#include <stdint.h>

#define N_NODES   50000
#define N_EDGES   800000
#define HID       128
#define N_GRAPHS  256
#define OUT_F     8
#define NEG_SLOPE 0.2f

#define SCAN_BLK  1024
#define N_SBLK    ((N_NODES + SCAN_BLK - 1) / SCAN_BLK)   // 49

// ---------------------------------------------------------------------------
// Scratch (device globals: no allocation allowed in kernel_launch)
// ---------------------------------------------------------------------------
__device__ float g_h [(size_t)N_NODES * HID];
__device__ float g_xb[(size_t)N_NODES * HID];
__device__ float g_as[N_NODES];
__device__ float g_ad[N_NODES];
__device__ int   g_deg[N_NODES];
__device__ int   g_rowptr[N_NODES + 1];
__device__ int   g_woff[N_NODES];
__device__ int   g_bsum[N_SBLK];
__device__ int   g_srcA[N_EDGES];
__device__ int   g_dstA[N_EDGES];
__device__ int   g_esrc[N_EDGES];
__device__ int   g_flag;
// pre-converted bf16 hi/lo weights, transposed to [n][k]
__device__ __nv_bfloat16 g_wbh0[128 * 256], g_wbl0[128 * 256];
__device__ __nv_bfloat16 g_wbh1[128 * 128], g_wbl1[128 * 128];
__device__ __nv_bfloat16 g_wbh2[128 * 128], g_wbl2[128 * 128];

// ---------------------------------------------------------------------------
// detect dtype + zero degree array (fused)
// ---------------------------------------------------------------------------
__global__ void detzero_kernel(const void* eidx) {
    int i = blockIdx.x * blockDim.x + threadIdx.x;
    if (i < N_NODES) g_deg[i] = 0;
    if (blockIdx.x == 0 && threadIdx.x < 32) {
        const int* p = (const int*)eidx;
        int lane = threadIdx.x;
        int nz = 0;
        for (int j = lane; j < 256; j += 32) {
            long long pos = (long long)j * (2LL * N_EDGES / 256);
            nz |= (p[pos | 1] != 0);
        }
        unsigned b = __ballot_sync(0xFFFFFFFFu, nz);
        if (lane == 0) g_flag = (b == 0) ? 1 : 0;
    }
}

__global__ void convert_hist_kernel(const void* eidx) {
    int e = blockIdx.x * blockDim.x + threadIdx.x;
    if (e >= N_EDGES) return;
    int s, d;
    if (g_flag) {
        const long long* p = (const long long*)eidx;
        s = (int)p[e];
        d = (int)p[e + N_EDGES];
    } else {
        const int* p = (const int*)eidx;
        s = p[e];
        d = p[e + N_EDGES];
    }
    g_srcA[e] = s;
    g_dstA[e] = d;
    atomicAdd(&g_deg[d], 1);
}

// scan stage 1: block-local inclusive scan + block sums
__global__ __launch_bounds__(SCAN_BLK)
void scan1_kernel() {
    __shared__ int s[SCAN_BLK];
    const int t = threadIdx.x;
    const int i = blockIdx.x * SCAN_BLK + t;
    int v = (i < N_NODES) ? g_deg[i] : 0;
    s[t] = v;
    __syncthreads();
    #pragma unroll
    for (int off = 1; off < SCAN_BLK; off <<= 1) {
        int u = (t >= off) ? s[t - off] : 0;
        __syncthreads();
        s[t] += u;
        __syncthreads();
    }
    if (i < N_NODES) g_rowptr[i] = s[t] - v;
    if (t == SCAN_BLK - 1) g_bsum[blockIdx.x] = s[t];
}

// scan stages 2+3 fused: each block reduces preceding block sums itself
__global__ __launch_bounds__(SCAN_BLK)
void scan23_kernel() {
    __shared__ int ssum[2];
    const int t = threadIdx.x;
    if (t < 64) {
        int v = (t < blockIdx.x) ? g_bsum[t] : 0;
        #pragma unroll
        for (int o = 16; o; o >>= 1) v += __shfl_xor_sync(0xFFFFFFFFu, v, o);
        if ((t & 31) == 0) ssum[t >> 5] = v;
    }
    __syncthreads();
    const int off = ssum[0] + ssum[1];
    const int i = blockIdx.x * SCAN_BLK + t;
    if (i < N_NODES) {
        int r = g_rowptr[i] + off;
        g_rowptr[i] = r;
        g_woff[i]   = r;
    }
    if (i == 0) g_rowptr[N_NODES] = N_EDGES;
}

__global__ void scatter_kernel() {
    int e = blockIdx.x * blockDim.x + threadIdx.x;
    if (e >= N_EDGES) return;
    int d = g_dstA[e];
    int p = atomicAdd(&g_woff[d], 1);
    g_esrc[p] = g_srcA[e];
}

// ---------------------------------------------------------------------------
// Weight pre-conversion: W[k][n] fp32 -> bf16 hi/lo transposed [n][k]
// ---------------------------------------------------------------------------
__global__ void wprep_kernel(const float* __restrict__ W,
                             __nv_bfloat16* __restrict__ bh,
                             __nv_bfloat16* __restrict__ bl, int K) {
    int idx = blockIdx.x * blockDim.x + threadIdx.x;
    if (idx >= 128 * K) return;
    int n = idx / K;
    int k = idx - n * K;
    float v = W[(size_t)k * HID + n];
    __nv_bfloat16 h = __float2bfloat16(v);
    bh[idx] = h;
    bl[idx] = __float2bfloat16(v - __bfloat162float(h));
}

// ---------------------------------------------------------------------------
// Tensor-core GEMM (mma.sync m16n8k16 bf16, split hi/lo, fp32 accum).
// BM=BN=128, BK=32, double-buffered SMEM, XOR-swizzled conflict-free layout.
// Fused epilogue: g_as/g_ad dots via SMEM stage.
// ---------------------------------------------------------------------------
#define GEMM_THREADS 256
#define BUF_BYTES 32768            // per buffer: AH/AL/BH/BL, 8KB each
#define STAGE_STRIDE 129
#define SM_TOTAL (128 * STAGE_STRIDE * 4)   // 66048 >= 2*BUF_BYTES

__device__ __forceinline__ void mma16816(float* d,
                                         uint32_t a0, uint32_t a1, uint32_t a2, uint32_t a3,
                                         uint32_t b0, uint32_t b1) {
    asm volatile(
        "mma.sync.aligned.m16n8k16.row.col.f32.bf16.bf16.f32 "
        "{%0,%1,%2,%3}, {%4,%5,%6,%7}, {%8,%9}, {%0,%1,%2,%3};"
        : "+f"(d[0]), "+f"(d[1]), "+f"(d[2]), "+f"(d[3])
        : "r"(a0), "r"(a1), "r"(a2), "r"(a3), "r"(b0), "r"(b1));
}

template <int K>
__global__ __launch_bounds__(GEMM_THREADS, 2)
void mma_gemm_kernel(const float* __restrict__ A,
                     const __nv_bfloat16* __restrict__ bhT,
                     const __nv_bfloat16* __restrict__ blT,
                     float* __restrict__ C,
                     const float* __restrict__ aw, const float* __restrict__ dw,
                     int M) {
    extern __shared__ char smem[];
    const int tid  = threadIdx.x;
    const int wid  = tid >> 5;
    const int lane = tid & 31;
    const int wm   = wid >> 2;          // 0..1
    const int wn   = wid & 3;           // 0..3
    const int lr   = lane >> 2;         // 0..7
    const int lc   = (lane & 3) << 1;   // 0,2,4,6
    const int m0   = blockIdx.x * 128;

    float acc[4][4][4] = {};

    auto fill = [&](int ch, int buf) {
        __nv_bfloat16* AH = (__nv_bfloat16*)(smem + buf * BUF_BYTES);
        __nv_bfloat16* AL = AH + 4096;
        __nv_bfloat16* BH = AH + 8192;
        __nv_bfloat16* BL = AH + 12288;
        const int k0 = ch * 32;
        // A: 128 rows x 32 k, fp32 -> bf16 hi/lo, swizzled (k ^ (row&7)<<2)
        #pragma unroll
        for (int i = tid; i < 128 * 16; i += GEMM_THREADS) {
            int r  = i >> 4;
            int kk = (i & 15) << 1;
            float2 v = make_float2(0.f, 0.f);
            if (m0 + r < M)
                v = *(const float2*)&A[(size_t)(m0 + r) * K + k0 + kk];
            __nv_bfloat16 hx = __float2bfloat16(v.x);
            __nv_bfloat16 hy = __float2bfloat16(v.y);
            __nv_bfloat16 lx = __float2bfloat16(v.x - __bfloat162float(hx));
            __nv_bfloat16 ly = __float2bfloat16(v.y - __bfloat162float(hy));
            int o = r * 32 + (kk ^ ((r & 7) << 2));
            *(__nv_bfloat162*)&AH[o] = __halves2bfloat162(hx, hy);
            *(__nv_bfloat162*)&AL[o] = __halves2bfloat162(lx, ly);
        }
        // B: pre-converted bf16, copy 4-elem groups, same swizzle
        #pragma unroll
        for (int i = tid; i < 128 * 8; i += GEMM_THREADS) {
            int n  = i >> 3;
            int k4 = (i & 7) << 2;
            uint2 h = *(const uint2*)&bhT[(size_t)n * K + k0 + k4];
            uint2 l = *(const uint2*)&blT[(size_t)n * K + k0 + k4];
            int o = n * 32 + (k4 ^ ((n & 7) << 2));
            *(uint2*)&BH[o] = h;
            *(uint2*)&BL[o] = l;
        }
    };

    fill(0, 0);
    __syncthreads();

    constexpr int NCH = K / 32;
    #pragma unroll 1
    for (int ch = 0; ch < NCH; ch++) {
        if (ch + 1 < NCH) fill(ch + 1, (ch + 1) & 1);   // prefetch next buffer
        __nv_bfloat16* AH = (__nv_bfloat16*)(smem + (ch & 1) * BUF_BYTES);
        __nv_bfloat16* AL = AH + 4096;
        __nv_bfloat16* BH = AH + 8192;
        __nv_bfloat16* BL = AH + 12288;

        #pragma unroll
        for (int ks = 0; ks < 32; ks += 16) {
            const int sw = lr << 2;
            uint32_t bh[4][2], bl[4][2];
            #pragma unroll
            for (int nt = 0; nt < 4; nt++) {
                int n  = wn * 32 + nt * 8 + lr;
                int o1 = n * 32 + ((lc + ks) ^ sw);
                int o2 = n * 32 + ((lc + ks + 8) ^ sw);
                bh[nt][0] = *(const uint32_t*)&BH[o1];
                bh[nt][1] = *(const uint32_t*)&BH[o2];
                bl[nt][0] = *(const uint32_t*)&BL[o1];
                bl[nt][1] = *(const uint32_t*)&BL[o2];
            }
            #pragma unroll
            for (int mt = 0; mt < 4; mt++) {
                int r  = wm * 64 + mt * 16 + lr;
                int o1 = r * 32 + ((lc + ks) ^ sw);
                int o2 = r * 32 + ((lc + ks + 8) ^ sw);
                uint32_t a0 = *(const uint32_t*)&AH[o1];
                uint32_t a1 = *(const uint32_t*)&AH[o1 + 256];   // row+8
                uint32_t a2 = *(const uint32_t*)&AH[o2];
                uint32_t a3 = *(const uint32_t*)&AH[o2 + 256];
                uint32_t l0 = *(const uint32_t*)&AL[o1];
                uint32_t l1 = *(const uint32_t*)&AL[o1 + 256];
                uint32_t l2 = *(const uint32_t*)&AL[o2];
                uint32_t l3 = *(const uint32_t*)&AL[o2 + 256];
                #pragma unroll
                for (int nt = 0; nt < 4; nt++) {
                    mma16816(acc[mt][nt], a0, a1, a2, a3, bh[nt][0], bh[nt][1]);
                    mma16816(acc[mt][nt], a0, a1, a2, a3, bl[nt][0], bl[nt][1]);
                    mma16816(acc[mt][nt], l0, l1, l2, l3, bh[nt][0], bh[nt][1]);
                }
            }
        }
        __syncthreads();
    }

    // --- stage C tile in SMEM (fp32, padded) ---
    float* stage = (float*)smem;
    #pragma unroll
    for (int mt = 0; mt < 4; mt++) {
        int r = wm * 64 + mt * 16 + lr;
        #pragma unroll
        for (int nt = 0; nt < 4; nt++) {
            int c = wn * 32 + nt * 8 + lc;
            stage[r * STAGE_STRIDE + c]           = acc[mt][nt][0];
            stage[r * STAGE_STRIDE + c + 1]       = acc[mt][nt][1];
            stage[(r + 8) * STAGE_STRIDE + c]     = acc[mt][nt][2];
            stage[(r + 8) * STAGE_STRIDE + c + 1] = acc[mt][nt][3];
        }
    }
    __syncthreads();

    // --- fused alpha dots (one thread per row) ---
    if (tid < 128) {
        float s = 0.f, d = 0.f;
        #pragma unroll 16
        for (int c = 0; c < HID; c++) {
            float v = stage[tid * STAGE_STRIDE + c];
            s = fmaf(v, aw[c], s);
            d = fmaf(v, dw[c], d);
        }
        if (m0 + tid < M) {
            g_as[m0 + tid] = s;
            g_ad[m0 + tid] = d;
        }
    }
    // --- coalesced C store ---
    #pragma unroll 4
    for (int idx = tid; idx < 128 * 128; idx += GEMM_THREADS) {
        int r = idx >> 7;
        int c = idx & 127;
        if (m0 + r < M)
            C[(size_t)(m0 + r) * HID + c] = stage[r * STAGE_STRIDE + c];
    }
}

// ---------------------------------------------------------------------------
// Segment softmax + weighted aggregation, one warp per node (no atomics).
// ---------------------------------------------------------------------------
#define NPB 8
#define DEG_CAP 96
__global__ __launch_bounds__(256)
void gat_agg_kernel(const float* __restrict__ h,
                    const float* __restrict__ bias,
                    float* __restrict__ xout, int do_relu) {
    __shared__ float cache[NPB][DEG_CAP];
    const int warp = threadIdx.x >> 5;
    const int lane = threadIdx.x & 31;
    const int node = blockIdx.x * NPB + warp;
    if (node >= N_NODES) return;

    const int beg = g_rowptr[node];
    const int end = g_rowptr[node + 1];
    const int deg = end - beg;
    const int col = lane * 4;

    float4 acc = make_float4(0.f, 0.f, 0.f, 0.f);

    if (deg > 0) {
        const float adn = g_ad[node];
        float m = -3.0e38f;
        if (deg <= DEG_CAP) {
            for (int j = lane; j < deg; j += 32) {
                float l = g_as[g_esrc[beg + j]] + adn;
                l = fmaxf(l, NEG_SLOPE * l);
                cache[warp][j] = l;
                m = fmaxf(m, l);
            }
            #pragma unroll
            for (int o = 16; o; o >>= 1) m = fmaxf(m, __shfl_xor_sync(0xFFFFFFFFu, m, o));
            __syncwarp();
            float ss = 0.f;
            for (int j = lane; j < deg; j += 32) {
                float e = __expf(cache[warp][j] - m);
                cache[warp][j] = e;
                ss += e;
            }
            #pragma unroll
            for (int o = 16; o; o >>= 1) ss += __shfl_xor_sync(0xFFFFFFFFu, ss, o);
            const float inv = 1.0f / ss;
            __syncwarp();

            int j = 0;
            for (; j + 4 <= deg; j += 4) {
                int b0 = beg + j;
                int s0 = g_esrc[b0 + 0], s1 = g_esrc[b0 + 1];
                int s2 = g_esrc[b0 + 2], s3 = g_esrc[b0 + 3];
                float c0 = cache[warp][j + 0] * inv;
                float c1 = cache[warp][j + 1] * inv;
                float c2 = cache[warp][j + 2] * inv;
                float c3 = cache[warp][j + 3] * inv;
                float4 h0 = *(const float4*)&h[(size_t)s0 * HID + col];
                float4 h1 = *(const float4*)&h[(size_t)s1 * HID + col];
                float4 h2 = *(const float4*)&h[(size_t)s2 * HID + col];
                float4 h3 = *(const float4*)&h[(size_t)s3 * HID + col];
                acc.x = fmaf(c0, h0.x, fmaf(c1, h1.x, fmaf(c2, h2.x, fmaf(c3, h3.x, acc.x))));
                acc.y = fmaf(c0, h0.y, fmaf(c1, h1.y, fmaf(c2, h2.y, fmaf(c3, h3.y, acc.y))));
                acc.z = fmaf(c0, h0.z, fmaf(c1, h1.z, fmaf(c2, h2.z, fmaf(c3, h3.z, acc.z))));
                acc.w = fmaf(c0, h0.w, fmaf(c1, h1.w, fmaf(c2, h2.w, fmaf(c3, h3.w, acc.w))));
            }
            for (; j < deg; j++) {
                int s = g_esrc[beg + j];
                float c = cache[warp][j] * inv;
                float4 hv = *(const float4*)&h[(size_t)s * HID + col];
                acc.x = fmaf(c, hv.x, acc.x);
                acc.y = fmaf(c, hv.y, acc.y);
                acc.z = fmaf(c, hv.z, acc.z);
                acc.w = fmaf(c, hv.w, acc.w);
            }
        } else {
            for (int j = lane; j < deg; j += 32) {
                float l = g_as[g_esrc[beg + j]] + adn;
                l = fmaxf(l, NEG_SLOPE * l);
                m = fmaxf(m, l);
            }
            #pragma unroll
            for (int o = 16; o; o >>= 1) m = fmaxf(m, __shfl_xor_sync(0xFFFFFFFFu, m, o));
            float ss = 0.f;
            for (int j = lane; j < deg; j += 32) {
                float l = g_as[g_esrc[beg + j]] + adn;
                l = fmaxf(l, NEG_SLOPE * l);
                ss += __expf(l - m);
            }
            #pragma unroll
            for (int o = 16; o; o >>= 1) ss += __shfl_xor_sync(0xFFFFFFFFu, ss, o);
            const float inv = 1.0f / ss;
            for (int j = 0; j < deg; j++) {
                int s = g_esrc[beg + j];
                float l = g_as[s] + adn;
                l = fmaxf(l, NEG_SLOPE * l);
                float c = __expf(l - m) * inv;
                float4 hv = *(const float4*)&h[(size_t)s * HID + col];
                acc.x = fmaf(c, hv.x, acc.x);
                acc.y = fmaf(c, hv.y, acc.y);
                acc.z = fmaf(c, hv.z, acc.z);
                acc.w = fmaf(c, hv.w, acc.w);
            }
        }
    }

    float4 b4 = *(const float4*)&bias[col];
    float4 o;
    o.x = acc.x + b4.x;
    o.y = acc.y + b4.y;
    o.z = acc.z + b4.z;
    o.w = acc.w + b4.w;
    if (do_relu) {
        o.x = fmaxf(o.x, 0.f);
        o.y = fmaxf(o.y, 0.f);
        o.z = fmaxf(o.z, 0.f);
        o.w = fmaxf(o.w, 0.f);
    }
    *(float4*)&xout[(size_t)node * HID + col] = o;
}

// ---------------------------------------------------------------------------
// Mean-pool per graph + linear head
// ---------------------------------------------------------------------------
__device__ __forceinline__ long long batch_val(const void* p, int i) {
    return g_flag ? ((const long long*)p)[i] : (long long)((const int*)p)[i];
}
__device__ int lower_bound_batch(const void* p, long long v) {
    int lo = 0, hi = N_NODES;
    while (lo < hi) {
        int mid = (lo + hi) >> 1;
        if (batch_val(p, mid) < v) lo = mid + 1; else hi = mid;
    }
    return lo;
}

__global__ __launch_bounds__(128)
void pool_head_kernel(const float* __restrict__ hfin, const void* __restrict__ batch,
                      const float* __restrict__ lin_w, const float* __restrict__ lin_b,
                      float* __restrict__ out) {
    const int g = blockIdx.x;
    const int j = threadIdx.x;
    const int lo = lower_bound_batch(batch, (long long)g);
    const int hi = lower_bound_batch(batch, (long long)g + 1);
    float sum = 0.f;
    for (int n = lo; n < hi; n++) sum += hfin[(size_t)n * HID + j];
    float cnt = (float)(hi - lo);
    __shared__ float sp[HID];
    sp[j] = sum / fmaxf(cnt, 1.0f);
    __syncthreads();
    if (j < OUT_F) {
        float acc = lin_b[j];
        #pragma unroll 16
        for (int k = 0; k < HID; k++) acc = fmaf(sp[k], lin_w[k * OUT_F + j], acc);
        out[g * OUT_F + j] = acc;
    }
}

// ---------------------------------------------------------------------------
// Launch
// ---------------------------------------------------------------------------
extern "C" void kernel_launch(void* const* d_in, const int* in_sizes, int n_in,
                              void* d_out, int out_size) {
    const float* x      = (const float*)d_in[0];
    const void*  eidx   = d_in[1];
    // d_in[2] edge_attr unused (reference else-branch)
    const void*  batch  = d_in[3];
    const float* W0     = (const float*)d_in[4];
    const float* asw0   = (const float*)d_in[5];
    const float* adw0   = (const float*)d_in[6];
    const float* b0     = (const float*)d_in[7];
    const float* W1     = (const float*)d_in[8];
    const float* asw1   = (const float*)d_in[9];
    const float* adw1   = (const float*)d_in[10];
    const float* b1     = (const float*)d_in[11];
    const float* W2     = (const float*)d_in[12];
    const float* asw2   = (const float*)d_in[13];
    const float* adw2   = (const float*)d_in[14];
    const float* b2     = (const float*)d_in[15];
    const float* lin_w  = (const float*)d_in[16];
    const float* lin_b  = (const float*)d_in[17];
    float* out = (float*)d_out;

    float* d_h;  cudaGetSymbolAddress((void**)&d_h,  g_h);
    float* d_xb; cudaGetSymbolAddress((void**)&d_xb, g_xb);
    __nv_bfloat16 *wbh0, *wbl0, *wbh1, *wbl1, *wbh2, *wbl2;
    cudaGetSymbolAddress((void**)&wbh0, g_wbh0);
    cudaGetSymbolAddress((void**)&wbl0, g_wbl0);
    cudaGetSymbolAddress((void**)&wbh1, g_wbh1);
    cudaGetSymbolAddress((void**)&wbl1, g_wbl1);
    cudaGetSymbolAddress((void**)&wbh2, g_wbh2);
    cudaGetSymbolAddress((void**)&wbl2, g_wbl2);

    static bool inited = false;
    static cudaStream_t s2;
    static cudaEvent_t evFork, evJoin;
    if (!inited) {
        cudaStreamCreateWithFlags(&s2, cudaStreamNonBlocking);
        cudaEventCreateWithFlags(&evFork, cudaEventDisableTiming);
        cudaEventCreateWithFlags(&evJoin, cudaEventDisableTiming);
        cudaFuncSetAttribute(mma_gemm_kernel<256>,
                             cudaFuncAttributeMaxDynamicSharedMemorySize, SM_TOTAL);
        cudaFuncSetAttribute(mma_gemm_kernel<128>,
                             cudaFuncAttributeMaxDynamicSharedMemorySize, SM_TOTAL);
        inited = true;
    }

    const int EB = (N_EDGES + 255) / 256;
    const int NB = (N_NODES + 255) / 256;
    const int MB = (N_NODES + 127) / 128;
    const int GB = (N_NODES + NPB - 1) / NPB;

    // --- fork: preprocessing + W1/W2 prep on s2, GEMM0 path on main stream ---
    cudaEventRecord(evFork, 0);
    cudaStreamWaitEvent(s2, evFork, 0);

    detzero_kernel<<<NB, 256, 0, s2>>>(eidx);
    convert_hist_kernel<<<EB, 256, 0, s2>>>(eidx);
    scan1_kernel<<<N_SBLK, SCAN_BLK, 0, s2>>>();
    scan23_kernel<<<N_SBLK, SCAN_BLK, 0, s2>>>();
    scatter_kernel<<<EB, 256, 0, s2>>>();
    wprep_kernel<<<(128 * 128 + 255) / 256, 256, 0, s2>>>(W1, wbh1, wbl1, 128);
    wprep_kernel<<<(128 * 128 + 255) / 256, 256, 0, s2>>>(W2, wbh2, wbl2, 128);
    cudaEventRecord(evJoin, s2);

    // main stream: W0 prep + GEMM0 overlap the preprocessing chain
    wprep_kernel<<<(128 * 256 + 255) / 256, 256>>>(W0, wbh0, wbl0, 256);
    mma_gemm_kernel<256><<<MB, GEMM_THREADS, SM_TOTAL>>>(x, wbh0, wbl0, d_h, asw0, adw0, N_NODES);

    // join: aggregation needs CSR + alpha
    cudaStreamWaitEvent(0, evJoin, 0);

    gat_agg_kernel<<<GB, 256>>>(d_h, b0, d_xb, 1);
    mma_gemm_kernel<128><<<MB, GEMM_THREADS, SM_TOTAL>>>(d_xb, wbh1, wbl1, d_h, asw1, adw1, N_NODES);
    gat_agg_kernel<<<GB, 256>>>(d_h, b1, d_xb, 1);
    mma_gemm_kernel<128><<<MB, GEMM_THREADS, SM_TOTAL>>>(d_xb, wbh2, wbl2, d_h, asw2, adw2, N_NODES);
    gat_agg_kernel<<<GB, 256>>>(d_h, b2, d_xb, 0);

    pool_head_kernel<<<N_GRAPHS, 128>>>(d_xb, batch, lin_w, lin_b, out);
}